// round 1
// baseline (speedup 1.0000x reference)
#include <cuda_runtime.h>
#include <cstdint>

#define FULLMASK 0xFFFFFFFFu

// ---------------- problem constants ----------------
#define BATCH   32
#define CDIM    256
#define HW      4096                      // H*W = 64*64
#define NPIX    (BATCH * HW)              // 131072 pixel vectors
#define NCODE   1024

#define ZQ_ELEMS  33554432LL              // 32*256*64*64
#define LOSS_OFF  (ZQ_ELEMS)
#define CLS_OFF   (ZQ_ELEMS + 1)
#define IDX_OFF   (ZQ_ELEMS + 2)

// ---------------- tiling ----------------
#define MB      128        // pixels per block
#define NTILE   128        // codes per N tile
#define KCHUNK  32         // K per smem chunk
#define THREADS 256

// ---------------- smem layout (bytes) ----------------
// region0: Zs float[256][128] = 131072B  (GEMM)  /  Zq float[128][260] = 133120B (scatter)
// region1: Cs float[32][132]  = 16896B   (GEMM)
// region2: small scratch
#define OFF_ZS    0
#define ZQ_LD     260
#define OFF_CS    133120
#define CS_LD     132
#define OFF_ZSQP  150016   // float[128][9]
#define OFF_ZSQ   154624   // float[128]
#define OFF_IDX   155136   // int[128]
#define OFF_LOSS  155648   // float[128]
#define SMEM_BYTES 156160

static __device__ float g_ce[NCODE];        // ||codebook_row||^2
static __device__ float g_partials[NPIX / MB];

// ---------------- packed f32x2 helpers ----------------
__device__ __forceinline__ void fma2(unsigned long long& d,
                                     unsigned long long a,
                                     unsigned long long b) {
    asm("fma.rn.f32x2 %0, %1, %2, %0;" : "+l"(d) : "l"(a), "l"(b));
}
__device__ __forceinline__ unsigned long long bcast2(float x) {
    unsigned long long r;
    asm("mov.b64 %0, {%1, %1};" : "=l"(r) : "f"(x));
    return r;
}
__device__ __forceinline__ float2 unpack2(unsigned long long v) {
    float2 r;
    asm("mov.b64 {%0, %1}, %2;" : "=f"(r.x), "=f"(r.y) : "l"(v));
    return r;
}

// ---------------- kernel 1: codebook row norms ----------------
__global__ void ce_kernel(const float* __restrict__ cb) {
    int row = blockIdx.x;
    int t = threadIdx.x;  // 64 threads, 4 floats each
    float4 v = *(const float4*)(cb + (size_t)row * CDIM + t * 4);
    float s = v.x * v.x + v.y * v.y + v.z * v.z + v.w * v.w;
    #pragma unroll
    for (int o = 16; o > 0; o >>= 1) s += __shfl_down_sync(FULLMASK, s, o);
    __shared__ float ws[2];
    if ((t & 31) == 0) ws[t >> 5] = s;
    __syncthreads();
    if (t == 0) g_ce[row] = ws[0] + ws[1];
}

// ---------------- kernel 2: fused distance-GEMM + argmin + gather + loss ----------------
__global__ void __launch_bounds__(THREADS, 1)
vq_kernel(const float* __restrict__ z, const float* __restrict__ cb,
          float* __restrict__ out) {
    extern __shared__ char smem[];
    float* Zs   = (float*)(smem + OFF_ZS);     // [k][128]
    float* Cs   = (float*)(smem + OFF_CS);     // [k][132]
    float* ZsqP = (float*)(smem + OFF_ZSQP);   // [128][9]
    float* Zsq  = (float*)(smem + OFF_ZSQ);    // [128]
    int*   SIdx = (int*)  (smem + OFF_IDX);    // [128]
    float* SLos = (float*)(smem + OFF_LOSS);   // [128]
    float* Zq   = (float*)(smem + OFF_ZS);     // reuse: [128][260]

    const int t  = threadIdx.x;
    const int tx = t & 15;        // n group
    const int ty = t >> 4;        // m group
    const int p0  = blockIdx.x * MB;
    const int b   = p0 >> 12;     // p0 / 4096
    const int hw0 = p0 & 4095;

    // ---- load full z tile [256 k][128 m] once; accumulate ||z||^2 partials ----
    const float* zp = z + ((size_t)b * CDIM) * HW + hw0;
    {
        float p0s = 0.f, p1s = 0.f, p2s = 0.f, p3s = 0.f;
        const int m4 = t & 31;
        #pragma unroll 8
        for (int i = 0; i < 32; i++) {
            int lin4 = t + i * 256;
            int k = lin4 >> 5;
            float4 v = *(const float4*)(zp + (size_t)k * HW + m4 * 4);
            *(float4*)(Zs + k * MB + m4 * 4) = v;
            p0s += v.x * v.x; p1s += v.y * v.y; p2s += v.z * v.z; p3s += v.w * v.w;
        }
        int slot = t >> 5;
        ZsqP[(m4 * 4 + 0) * 9 + slot] = p0s;
        ZsqP[(m4 * 4 + 1) * 9 + slot] = p1s;
        ZsqP[(m4 * 4 + 2) * 9 + slot] = p2s;
        ZsqP[(m4 * 4 + 3) * 9 + slot] = p3s;
    }
    __syncthreads();
    if (t < MB) {
        float s = 0.f;
        #pragma unroll
        for (int j = 0; j < 8; j++) s += ZsqP[t * 9 + j];
        Zsq[t] = s;
    }

    // ---- main loop: N tiles of 128 codes ----
    float best[8];
    int   bidx[8];
    #pragma unroll
    for (int mi = 0; mi < 8; mi++) { best[mi] = 3.4e38f; bidx[mi] = 0; }

    for (int nt = 0; nt < NCODE / NTILE; nt++) {
        unsigned long long acc[8][4];
        #pragma unroll
        for (int mi = 0; mi < 8; mi++)
            #pragma unroll
            for (int np = 0; np < 4; np++) acc[mi][np] = 0ull;

        const float* cbase = cb + (size_t)(nt * NTILE) * CDIM;

        for (int kc = 0; kc < CDIM / KCHUNK; kc++) {
            __syncthreads();
            // load 128n x 32k codebook chunk, transposed into Cs[k][n]
            const float* cbp = cbase + kc * KCHUNK;
            #pragma unroll
            for (int i = 0; i < 4; i++) {
                int lin4 = t + i * 256;
                int n  = lin4 >> 3;
                int k4 = lin4 & 7;
                float4 v = *(const float4*)(cbp + (size_t)n * CDIM + k4 * 4);
                Cs[(4 * k4 + 0) * CS_LD + n] = v.x;
                Cs[(4 * k4 + 1) * CS_LD + n] = v.y;
                Cs[(4 * k4 + 2) * CS_LD + n] = v.z;
                Cs[(4 * k4 + 3) * CS_LD + n] = v.w;
            }
            __syncthreads();

            const float* ZsK = Zs + (kc * KCHUNK) * MB;
            #pragma unroll 8
            for (int k = 0; k < KCHUNK; k++) {
                const float4* pa = (const float4*)(ZsK + k * MB + ty * 8);
                float4 a0 = pa[0], a1 = pa[1];
                const ulonglong2* pb = (const ulonglong2*)(Cs + k * CS_LD + tx * 8);
                ulonglong2 b01 = pb[0], b23 = pb[1];
                unsigned long long bb0 = b01.x, bb1 = b01.y, bb2 = b23.x, bb3 = b23.y;
                float am[8] = {a0.x, a0.y, a0.z, a0.w, a1.x, a1.y, a1.z, a1.w};
                #pragma unroll
                for (int mi = 0; mi < 8; mi++) {
                    unsigned long long az = bcast2(am[mi]);
                    fma2(acc[mi][0], az, bb0);
                    fma2(acc[mi][1], az, bb1);
                    fma2(acc[mi][2], az, bb2);
                    fma2(acc[mi][3], az, bb3);
                }
            }
        }

        // epilogue for this N tile: dist = ||c||^2 - 2*s ; keep running argmin
        #pragma unroll
        for (int mi = 0; mi < 8; mi++) {
            #pragma unroll
            for (int np = 0; np < 4; np++) {
                float2 s2 = unpack2(acc[mi][np]);
                int n0 = nt * NTILE + tx * 8 + 2 * np;
                float2 ce2 = *(const float2*)(g_ce + n0);
                float d0 = fmaf(-2.f, s2.x, ce2.x);
                float d1 = fmaf(-2.f, s2.y, ce2.y);
                if (d0 < best[mi]) { best[mi] = d0; bidx[mi] = n0; }
                if (d1 < best[mi]) { best[mi] = d1; bidx[mi] = n0 + 1; }
            }
        }
    }

    // ---- cross-thread argmin over the 16 tx lanes (xor-shuffle, width 16) ----
    #pragma unroll
    for (int off = 1; off < 16; off <<= 1) {
        #pragma unroll
        for (int mi = 0; mi < 8; mi++) {
            float ov = __shfl_xor_sync(FULLMASK, best[mi], off, 16);
            int   oi = __shfl_xor_sync(FULLMASK, bidx[mi], off, 16);
            if (ov < best[mi] || (ov == best[mi] && oi < bidx[mi])) {
                best[mi] = ov; bidx[mi] = oi;
            }
        }
    }
    if (tx == 0) {
        #pragma unroll
        for (int mi = 0; mi < 8; mi++) {
            int m = ty * 8 + mi;
            SIdx[m] = bidx[mi];
            SLos[m] = best[mi] + Zsq[m];          // ||z - e||^2 (expanded form)
            out[IDX_OFF + p0 + m] = (float)bidx[mi];
        }
    }
    __syncthreads();

    // deterministic per-block loss partial (fixed order)
    if (t == 0) {
        float s = 0.f;
        for (int m = 0; m < MB; m++) s += SLos[m];
        g_partials[blockIdx.x] = s;
    }

    // ---- gather codebook rows into smem staging (coalesced L2 reads) ----
    {
        int w = t >> 5, lane = t & 31;
        #pragma unroll 4
        for (int r = 0; r < 16; r++) {
            int m = w * 16 + r;
            const float4* crow = (const float4*)(cb + (size_t)SIdx[m] * CDIM);
            float4 f0 = crow[lane];
            float4 f1 = crow[lane + 32];
            *(float4*)(Zq + m * ZQ_LD + lane * 4)        = f0;
            *(float4*)(Zq + m * ZQ_LD + (lane + 32) * 4) = f1;
        }
    }
    __syncthreads();

    // ---- coalesced write-out of z_q in (B,C,H,W) layout ----
    {
        const int m = t & 127;
        const int chi = t >> 7;                       // 0 or 1
        float* obase = out + ((size_t)b * CDIM) * HW + hw0 + m;
        #pragma unroll 8
        for (int i = 0; i < 128; i++) {
            int c = chi + 2 * i;
            obase[(size_t)c * HW] = Zq[m * ZQ_LD + c];
        }
    }
}

// ---------------- kernel 3: deterministic loss finalize ----------------
__global__ void finalize_kernel(float* __restrict__ out) {
    __shared__ float s[1024];
    int t = threadIdx.x;
    s[t] = g_partials[t];
    __syncthreads();
    for (int st = 512; st > 0; st >>= 1) {
        if (t < st) s[t] += s[t + st];
        __syncthreads();
    }
    if (t == 0) {
        out[LOSS_OFF] = s[0] * (1.f / 33554432.f);
        out[CLS_OFF]  = 0.f;
    }
}

// ---------------- launch ----------------
extern "C" void kernel_launch(void* const* d_in, const int* in_sizes, int n_in,
                              void* d_out, int out_size) {
    (void)in_sizes; (void)n_in; (void)out_size;
    const float* z  = (const float*)d_in[0];
    const float* cb = (const float*)d_in[1];
    float* out = (float*)d_out;

    cudaFuncSetAttribute(vq_kernel, cudaFuncAttributeMaxDynamicSharedMemorySize,
                         SMEM_BYTES);

    ce_kernel<<<NCODE, 64>>>(cb);
    vq_kernel<<<NPIX / MB, THREADS, SMEM_BYTES>>>(z, cb, out);
    finalize_kernel<<<1, 1024>>>(out);
}